// round 14
// baseline (speedup 1.0000x reference)
#include <cuda_runtime.h>
#include <math.h>

#define NN 50000
#define EE 800000
#define IN_DIMC 32
#define HIDC 64
#define HEADSC 4
#define HCC 256
#define OUT_DIMC 128
#define LN_EPSF 1e-5f
#define NEG_SLOPEF 0.2f

typedef unsigned long long ull;

// ---------------- scratch (device globals; no allocation allowed) ----------------
__device__ float g_h0[NN * HIDC];
__device__ float g_feat[NN * HCC];
__device__ float g_agg[NN * HCC];
__device__ float g_asrc[NN * HEADSC];
__device__ float g_adst[NN * HEADSC];
__device__ int   g_deg[NN];
__device__ int   g_off[NN + 1];
__device__ int   g_cur[NN];
__device__ int   g_srclist[EE];
__device__ int   g_bsum[256];

__device__ __forceinline__ float eluf(float x) { return x > 0.f ? x : expm1f(x); }
__device__ __forceinline__ float lrelu(float x) { return x > 0.f ? x : NEG_SLOPEF * x; }

__device__ __forceinline__ void fma2(ull& d, ull a, ull b) {
    asm("fma.rn.f32x2 %0, %1, %2, %0;" : "+l"(d) : "l"(a), "l"(b));
}
__device__ __forceinline__ ull dupf(float a) {
    ull r;
    asm("mov.b64 %0, {%1, %1};" : "=l"(r) : "f"(a));
    return r;
}
__device__ __forceinline__ ull packf(float a, float b) {
    ull r;
    asm("mov.b64 %0, {%1, %2};" : "=l"(r) : "f"(a), "f"(b));
    return r;
}
__device__ __forceinline__ void unpackf(ull v, float& lo, float& hi) {
    asm("mov.b64 {%0, %1}, %2;" : "=f"(lo), "=f"(hi) : "l"(v));
}
__device__ __forceinline__ void cpasync16(unsigned smem_addr, const void* gptr) {
    asm volatile("cp.async.cg.shared.global [%0], [%1], 16;" :: "r"(smem_addr), "l"(gptr));
}
__device__ __forceinline__ unsigned smem_u32(const void* p) {
    return (unsigned)__cvta_generic_to_shared(p);
}

// ---------------- graph build ----------------
__global__ void zero_deg_kernel() {
    int i = blockIdx.x * blockDim.x + threadIdx.x;
    if (i < NN) g_deg[i] = 0;
}

__global__ void count_deg_kernel(const int* __restrict__ dst, int E) {
    int i = blockIdx.x * blockDim.x + threadIdx.x;
    if (i < E) atomicAdd(&g_deg[dst[i]], 1);
}

__global__ void scan_p1_kernel() {
    __shared__ int s[256];
    int t = threadIdx.x;
    int i = blockIdx.x * 256 + t;
    int v = (i < NN) ? g_deg[i] : 0;
    s[t] = v;
    __syncthreads();
#pragma unroll
    for (int d = 1; d < 256; d <<= 1) {
        int u = (t >= d) ? s[t - d] : 0;
        __syncthreads();
        s[t] += u;
        __syncthreads();
    }
    if (i < NN) g_off[i] = s[t] - v;
    if (t == 255) g_bsum[blockIdx.x] = s[255];
}

__global__ void scan_p2_kernel(int nblocks) {
    __shared__ int s[256];
    int t = threadIdx.x;
    int v = (t < nblocks) ? g_bsum[t] : 0;
    s[t] = v;
    __syncthreads();
#pragma unroll
    for (int d = 1; d < 256; d <<= 1) {
        int u = (t >= d) ? s[t - d] : 0;
        __syncthreads();
        s[t] += u;
        __syncthreads();
    }
    if (t < nblocks) g_bsum[t] = s[t] - v;
}

__global__ void scan_p3_kernel() {
    int i = blockIdx.x * 256 + threadIdx.x;
    if (i < NN) {
        int o = g_off[i] + g_bsum[blockIdx.x];
        g_off[i] = o;
        g_cur[i] = o;
        if (i == NN - 1) g_off[NN] = o + g_deg[i];
    }
}

__global__ void scatter_kernel(const int* __restrict__ src, const int* __restrict__ dst, int E) {
    int i = blockIdx.x * blockDim.x + threadIdx.x;
    if (i < E) {
        int p = atomicAdd(&g_cur[dst[i]], 1);
        g_srclist[p] = src[i];
    }
}

// ---------------- small SGEMM (input projection, N=64) ----------------
#define BM 64
#define BN 64
#define BK 16
__global__ void gemm_kernel(const float* __restrict__ A, const float* __restrict__ B,
                            const float* __restrict__ bias, float* __restrict__ C,
                            int M, int Ncol, int K, int act) {
    __shared__ float sA[BK][BM];
    __shared__ float sB[BK][BN];
    int tid = threadIdx.x;
    int bm = blockIdx.x * BM, bn = blockIdx.y * BN;
    int ty = tid / 16, tx = tid % 16;
    float acc[4][4] = {};
    int arow = tid >> 2;
    int akc  = (tid & 3) * 4;
    int brow = tid >> 4;
    int bcol = (tid & 15) * 4;

    for (int k0 = 0; k0 < K; k0 += BK) {
        float4 av = make_float4(0.f, 0.f, 0.f, 0.f);
        int gr = bm + arow;
        if (gr < M) av = *reinterpret_cast<const float4*>(A + (size_t)gr * K + k0 + akc);
        sA[akc + 0][arow] = av.x;
        sA[akc + 1][arow] = av.y;
        sA[akc + 2][arow] = av.z;
        sA[akc + 3][arow] = av.w;
        float4 bv = *reinterpret_cast<const float4*>(B + (size_t)(k0 + brow) * Ncol + bn + bcol);
        *reinterpret_cast<float4*>(&sB[brow][bcol]) = bv;
        __syncthreads();
#pragma unroll
        for (int k = 0; k < BK; k++) {
            float4 a4 = *reinterpret_cast<const float4*>(&sA[k][ty * 4]);
            float4 b4 = *reinterpret_cast<const float4*>(&sB[k][tx * 4]);
            float a[4] = {a4.x, a4.y, a4.z, a4.w};
            float b[4] = {b4.x, b4.y, b4.z, b4.w};
#pragma unroll
            for (int i = 0; i < 4; i++)
#pragma unroll
                for (int j = 0; j < 4; j++) acc[i][j] = fmaf(a[i], b[j], acc[i][j]);
        }
        __syncthreads();
    }
#pragma unroll
    for (int i = 0; i < 4; i++) {
        int r = bm + ty * 4 + i;
        if (r >= M) break;
#pragma unroll
        for (int j = 0; j < 4; j++) {
            int c = bn + tx * 4 + j;
            float v = acc[i][j];
            if (bias) v += bias[c];
            if (act) v = eluf(v);
            C[(size_t)r * Ncol + c] = v;
        }
    }
}

// ---------------- 96x128 SGEMM + attention epilogue (3 CTAs/SM, 3-stage cp.async) ----------------
#define TBM 96
#define TBN 128
#define TBK 16
#define TAPAD 100   // 400B row stride, 16B aligned

__global__ __launch_bounds__(256, 3) void gemm_att_kernel(
    const float* __restrict__ A, const float* __restrict__ B,
    float* __restrict__ C, const float* __restrict__ att_src,
    const float* __restrict__ att_dst, int M, int K) {
    __shared__ float sA[2][TBK][TAPAD];
    __shared__ float sB[3][TBK][TBN];
    __shared__ float s_as[TBN];
    __shared__ float s_ad[TBN];

    int tid = threadIdx.x;        // 256
    int bm = blockIdx.x * TBM;
    int bn = blockIdx.y * TBN;    // 0 or 128
    int w = tid >> 5;             // warp 0..7 -> rows 12w..12w+11
    int tx = tid & 31;            // cols bn + tx*4..+3

    if (tid < TBN) {
        s_as[tid] = att_src[bn + tid];
        s_ad[tid] = att_dst[bn + tid];
    }

    int arow = tid >> 1;          // 0..95 (valid when tid<192)
    int akc  = (tid & 1) * 8;     // 0 or 8
    bool aload = (tid < 192);
    int gr = bm + arow;
    bool avalid = aload && (gr < M);
    const float* Arow = A + (size_t)gr * K + akc;

    int lkb  = tid >> 4;          // 0..15
    int bcol = (tid & 15) * 8;    // 0..120
    const float* Bbase = B + (size_t)lkb * HCC + bn + bcol;

    ull acc[6][4];
#pragma unroll
    for (int p = 0; p < 6; p++)
#pragma unroll
        for (int j = 0; j < 4; j++) acc[p][j] = 0ull;

    const int T = K / TBK;

    float4 av0 = make_float4(0.f, 0.f, 0.f, 0.f);
    float4 av1 = make_float4(0.f, 0.f, 0.f, 0.f);
    if (avalid) {
        av0 = *reinterpret_cast<const float4*>(Arow);
        av1 = *reinterpret_cast<const float4*>(Arow + 4);
    }
    {
        unsigned d0 = smem_u32(&sB[0][lkb][bcol]);
        cpasync16(d0, Bbase);
        cpasync16(d0 + 16, Bbase + 4);
        asm volatile("cp.async.commit_group;");
        if (T > 1) {
            unsigned d1 = smem_u32(&sB[1][lkb][bcol]);
            const float* g1 = Bbase + (size_t)TBK * HCC;
            cpasync16(d1, g1);
            cpasync16(d1 + 16, g1 + 4);
            asm volatile("cp.async.commit_group;");
        }
    }

    int st = 0;
    int ab = 0;
    for (int t = 0; t < T; t++) {
        if (t + 1 < T) asm volatile("cp.async.wait_group 1;");
        else           asm volatile("cp.async.wait_group 0;");
        if (aload) {
            sA[ab][akc + 0][arow] = av0.x;
            sA[ab][akc + 1][arow] = av0.y;
            sA[ab][akc + 2][arow] = av0.z;
            sA[ab][akc + 3][arow] = av0.w;
            sA[ab][akc + 4][arow] = av1.x;
            sA[ab][akc + 5][arow] = av1.y;
            sA[ab][akc + 6][arow] = av1.z;
            sA[ab][akc + 7][arow] = av1.w;
        }
        __syncthreads();
        // issue B(t+2) EARLY: slot (st+2)%3 was last read during compute(t-1),
        // which every warp finished before the barrier above.
        if (t + 2 < T) {
            int ns = (st + 2 >= 3) ? st - 1 : st + 2;
            unsigned dn = smem_u32(&sB[ns][lkb][bcol]);
            const float* gn = Bbase + (size_t)(t + 2) * TBK * HCC;
            cpasync16(dn, gn);
            cpasync16(dn + 16, gn + 4);
        }
        asm volatile("cp.async.commit_group;");
        if (t + 1 < T && avalid) {
            av0 = *reinterpret_cast<const float4*>(Arow + (size_t)(t + 1) * TBK);
            av1 = *reinterpret_cast<const float4*>(Arow + (size_t)(t + 1) * TBK + 4);
        }
#pragma unroll
        for (int k = 0; k < TBK; k++) {
            longlong2 a01 = *reinterpret_cast<const longlong2*>(&sA[ab][k][w * 12]);
            longlong2 a23 = *reinterpret_cast<const longlong2*>(&sA[ab][k][w * 12 + 4]);
            longlong2 a45 = *reinterpret_cast<const longlong2*>(&sA[ab][k][w * 12 + 8]);
            float4 b4 = *reinterpret_cast<const float4*>(&sB[st][k][tx * 4]);
            ull ap[6] = {(ull)a01.x, (ull)a01.y, (ull)a23.x, (ull)a23.y, (ull)a45.x, (ull)a45.y};
            float b[4] = {b4.x, b4.y, b4.z, b4.w};
#pragma unroll
            for (int j = 0; j < 4; j++) {
                ull bd = dupf(b[j]);
#pragma unroll
                for (int p = 0; p < 6; p++) fma2(acc[p][j], ap[p], bd);
            }
        }
        st = (st + 1 == 3) ? 0 : st + 1;
        ab ^= 1;
    }

    int h = (bn >> 6) + (tx >> 4);
    float ws[4], wd[4];
#pragma unroll
    for (int q = 0; q < 4; q++) {
        ws[q] = s_as[tx * 4 + q];
        wd[q] = s_ad[tx * 4 + q];
    }

#pragma unroll
    for (int p = 0; p < 6; p++) {
#pragma unroll
        for (int half = 0; half < 2; half++) {
            int r = bm + w * 12 + 2 * p + half;
            float v[4];
            {
                float l0, h0, l1, h1, l2, h2, l3, h3;
                unpackf(acc[p][0], l0, h0);
                unpackf(acc[p][1], l1, h1);
                unpackf(acc[p][2], l2, h2);
                unpackf(acc[p][3], l3, h3);
                v[0] = half ? h0 : l0;
                v[1] = half ? h1 : l1;
                v[2] = half ? h2 : l2;
                v[3] = half ? h3 : l3;
            }
            float p1 = v[0] * ws[0] + v[1] * ws[1] + v[2] * ws[2] + v[3] * ws[3];
            float p2 = v[0] * wd[0] + v[1] * wd[1] + v[2] * wd[2] + v[3] * wd[3];
#pragma unroll
            for (int o = 8; o; o >>= 1) {
                p1 += __shfl_xor_sync(0xffffffffu, p1, o);
                p2 += __shfl_xor_sync(0xffffffffu, p2, o);
            }
            if (r < M) {
                if ((tx & 15) == 0) {
                    g_asrc[(size_t)r * HEADSC + h] = p1;
                    g_adst[(size_t)r * HEADSC + h] = p2;
                }
                *reinterpret_cast<float4*>(C + (size_t)r * HCC + bn + tx * 4) =
                    make_float4(v[0], v[1], v[2], v[3]);
            }
        }
    }
}

// ---------------- GAT aggregation: 2 destinations per warp (score-latency overlap) ----------------
#define AGG_WARPS 8
__global__ __launch_bounds__(AGG_WARPS * 32) void gat_fused_kernel(
    const float* __restrict__ feat, const float* __restrict__ bias,
    float* __restrict__ out) {
    __shared__ float s_p[AGG_WARPS][2][32][HEADSC];
    __shared__ int s_src[AGG_WARPS][2][32];

    int wid = threadIdx.x >> 5;
    int lane = threadIdx.x & 31;
    int d0 = (blockIdx.x * AGG_WARPS + wid) * 2;
    int d1 = d0 + 1;
    if (d0 >= NN) return;
    bool has1 = (d1 < NN);

    int base0 = g_off[d0];
    int total0 = g_off[d0 + 1] - base0 + 1;   // + self-loop
    int base1 = 0, total1 = 0;
    if (has1) {
        base1 = g_off[d1];
        total1 = g_off[d1 + 1] - base1 + 1;
    }
    int deg0 = total0 - 1, deg1 = total1 - 1;

    float4 a40 = *reinterpret_cast<const float4*>(g_adst + (size_t)d0 * HEADSC);
    float ad0[4] = {a40.x, a40.y, a40.z, a40.w};
    float ad1[4] = {0.f, 0.f, 0.f, 0.f};
    if (has1) {
        float4 a41 = *reinterpret_cast<const float4*>(g_adst + (size_t)d1 * HEADSC);
        ad1[0] = a41.x; ad1[1] = a41.y; ad1[2] = a41.z; ad1[3] = a41.w;
    }

    int myc = lane * 8;
    int myh = lane >> 3;
    float acc0[8] = {0.f, 0.f, 0.f, 0.f, 0.f, 0.f, 0.f, 0.f};
    float acc1[8] = {0.f, 0.f, 0.f, 0.f, 0.f, 0.f, 0.f, 0.f};
    float den0[4] = {0.f, 0.f, 0.f, 0.f};
    float den1[4] = {0.f, 0.f, 0.f, 0.f};

    int tmax = total0 > total1 ? total0 : total1;
    for (int ch = 0; ch < tmax; ch += 32) {
        int j = ch + lane;
        // score phase for BOTH dsts: two independent scattered-load batches in flight
        if (j < total0) {
            int s = (j < deg0) ? g_srclist[base0 + j] : d0;
            float4 as4 = *reinterpret_cast<const float4*>(g_asrc + (size_t)s * HEADSC);
            float p0 = __expf(lrelu(as4.x + ad0[0]));
            float p1 = __expf(lrelu(as4.y + ad0[1]));
            float p2 = __expf(lrelu(as4.z + ad0[2]));
            float p3 = __expf(lrelu(as4.w + ad0[3]));
            den0[0] += p0; den0[1] += p1; den0[2] += p2; den0[3] += p3;
            s_p[wid][0][lane][0] = p0;
            s_p[wid][0][lane][1] = p1;
            s_p[wid][0][lane][2] = p2;
            s_p[wid][0][lane][3] = p3;
            s_src[wid][0][lane] = s;
        }
        if (j < total1) {
            int s = (j < deg1) ? g_srclist[base1 + j] : d1;
            float4 as4 = *reinterpret_cast<const float4*>(g_asrc + (size_t)s * HEADSC);
            float p0 = __expf(lrelu(as4.x + ad1[0]));
            float p1 = __expf(lrelu(as4.y + ad1[1]));
            float p2 = __expf(lrelu(as4.z + ad1[2]));
            float p3 = __expf(lrelu(as4.w + ad1[3]));
            den1[0] += p0; den1[1] += p1; den1[2] += p2; den1[3] += p3;
            s_p[wid][1][lane][0] = p0;
            s_p[wid][1][lane][1] = p1;
            s_p[wid][1][lane][2] = p2;
            s_p[wid][1][lane][3] = p3;
            s_src[wid][1][lane] = s;
        }
        __syncwarp();
        int lim0 = total0 - ch; if (lim0 > 32) lim0 = 32; if (lim0 < 0) lim0 = 0;
        int lim1 = total1 - ch; if (lim1 > 32) lim1 = 32; if (lim1 < 0) lim1 = 0;
        int lim = lim0 > lim1 ? lim0 : lim1;
        // interleaved gather: two independent load/FMA streams
        for (int jj = 0; jj < lim; jj++) {
            if (jj < lim0) {
                int s = s_src[wid][0][jj];
                float a = s_p[wid][0][jj][myh];
                float4 fa = *reinterpret_cast<const float4*>(feat + (size_t)s * HCC + myc);
                float4 fb = *reinterpret_cast<const float4*>(feat + (size_t)s * HCC + myc + 4);
                acc0[0] = fmaf(a, fa.x, acc0[0]); acc0[1] = fmaf(a, fa.y, acc0[1]);
                acc0[2] = fmaf(a, fa.z, acc0[2]); acc0[3] = fmaf(a, fa.w, acc0[3]);
                acc0[4] = fmaf(a, fb.x, acc0[4]); acc0[5] = fmaf(a, fb.y, acc0[5]);
                acc0[6] = fmaf(a, fb.z, acc0[6]); acc0[7] = fmaf(a, fb.w, acc0[7]);
            }
            if (jj < lim1) {
                int s = s_src[wid][1][jj];
                float a = s_p[wid][1][jj][myh];
                float4 fa = *reinterpret_cast<const float4*>(feat + (size_t)s * HCC + myc);
                float4 fb = *reinterpret_cast<const float4*>(feat + (size_t)s * HCC + myc + 4);
                acc1[0] = fmaf(a, fa.x, acc1[0]); acc1[1] = fmaf(a, fa.y, acc1[1]);
                acc1[2] = fmaf(a, fa.z, acc1[2]); acc1[3] = fmaf(a, fa.w, acc1[3]);
                acc1[4] = fmaf(a, fb.x, acc1[4]); acc1[5] = fmaf(a, fb.y, acc1[5]);
                acc1[6] = fmaf(a, fb.z, acc1[6]); acc1[7] = fmaf(a, fb.w, acc1[7]);
            }
        }
        __syncwarp();
    }

#pragma unroll
    for (int o = 16; o; o >>= 1) {
#pragma unroll
        for (int h = 0; h < 4; h++) {
            den0[h] += __shfl_xor_sync(0xffffffffu, den0[h], o);
            den1[h] += __shfl_xor_sync(0xffffffffu, den1[h], o);
        }
    }

    const float* brow = bias + myc;
    float4 b0 = *reinterpret_cast<const float4*>(brow);
    float4 b1 = *reinterpret_cast<const float4*>(brow + 4);

    {
        float inv = 1.f / (den0[myh] + 1e-16f);
        float* orow = out + (size_t)d0 * HCC + myc;
        float4 r0 = make_float4(eluf(acc0[0] * inv + b0.x), eluf(acc0[1] * inv + b0.y),
                                eluf(acc0[2] * inv + b0.z), eluf(acc0[3] * inv + b0.w));
        float4 r1 = make_float4(eluf(acc0[4] * inv + b1.x), eluf(acc0[5] * inv + b1.y),
                                eluf(acc0[6] * inv + b1.z), eluf(acc0[7] * inv + b1.w));
        *reinterpret_cast<float4*>(orow) = r0;
        *reinterpret_cast<float4*>(orow + 4) = r1;
    }
    if (has1) {
        float inv = 1.f / (den1[myh] + 1e-16f);
        float* orow = out + (size_t)d1 * HCC + myc;
        float4 r0 = make_float4(eluf(acc1[0] * inv + b0.x), eluf(acc1[1] * inv + b0.y),
                                eluf(acc1[2] * inv + b0.z), eluf(acc1[3] * inv + b0.w));
        float4 r1 = make_float4(eluf(acc1[4] * inv + b1.x), eluf(acc1[5] * inv + b1.y),
                                eluf(acc1[6] * inv + b1.z), eluf(acc1[7] * inv + b1.w));
        *reinterpret_cast<float4*>(orow) = r0;
        *reinterpret_cast<float4*>(orow + 4) = r1;
    }
}

// ---------------- fused out projection + layernorm, double-buffered ----------------
#define ONB 32
__global__ __launch_bounds__(256) void onl_kernel(
    const float* __restrict__ hin, const float* __restrict__ Wout,
    const float* __restrict__ bout, const float* __restrict__ gamma,
    const float* __restrict__ beta, float* __restrict__ out) {
    __shared__ float sA[2][32][ONB + 1];
    __shared__ float sB[2][32][OUT_DIMC];
    int tid = threadIdx.x;  // 256
    int bm = blockIdx.x * ONB;
    int ty = tid >> 5;
    int tx = tid & 31;

    int lrow = tid >> 3;
    int lkc  = (tid & 7) * 4;
    int lkb  = tid >> 3;
    int lc16 = (tid & 7) * 16;

    ull acc[4][2];
#pragma unroll
    for (int i = 0; i < 4; i++) { acc[i][0] = 0ull; acc[i][1] = 0ull; }

    const int T = HCC / 32;  // 8
    int gr = bm + lrow;
    float4 a_pre = (gr < NN) ? *reinterpret_cast<const float4*>(hin + (size_t)gr * HCC + lkc)
                             : make_float4(0.f, 0.f, 0.f, 0.f);
    float4 b_pre[4];
#pragma unroll
    for (int q = 0; q < 4; q++)
        b_pre[q] = *reinterpret_cast<const float4*>(Wout + (size_t)lkb * OUT_DIMC + lc16 + q * 4);

    sA[0][lkc + 0][lrow] = a_pre.x;
    sA[0][lkc + 1][lrow] = a_pre.y;
    sA[0][lkc + 2][lrow] = a_pre.z;
    sA[0][lkc + 3][lrow] = a_pre.w;
#pragma unroll
    for (int q = 0; q < 4; q++)
        *reinterpret_cast<float4*>(&sB[0][lkb][lc16 + q * 4]) = b_pre[q];
    __syncthreads();

    int buf = 0;
    for (int t = 0; t < T; t++) {
        if (t + 1 < T) {
            int k0 = (t + 1) * 32;
            a_pre = (gr < NN) ? *reinterpret_cast<const float4*>(hin + (size_t)gr * HCC + k0 + lkc)
                              : make_float4(0.f, 0.f, 0.f, 0.f);
#pragma unroll
            for (int q = 0; q < 4; q++)
                b_pre[q] = *reinterpret_cast<const float4*>(Wout + (size_t)(k0 + lkb) * OUT_DIMC + lc16 + q * 4);
        }
#pragma unroll 8
        for (int k = 0; k < 32; k++) {
            float4 b4 = *reinterpret_cast<const float4*>(&sB[buf][k][tx * 4]);
            ull bp0 = packf(b4.x, b4.y);
            ull bp1 = packf(b4.z, b4.w);
#pragma unroll
            for (int i = 0; i < 4; i++) {
                ull ad = dupf(sA[buf][k][ty * 4 + i]);
                fma2(acc[i][0], ad, bp0);
                fma2(acc[i][1], ad, bp1);
            }
        }
        if (t + 1 < T) {
            int nb = buf ^ 1;
            sA[nb][lkc + 0][lrow] = a_pre.x;
            sA[nb][lkc + 1][lrow] = a_pre.y;
            sA[nb][lkc + 2][lrow] = a_pre.z;
            sA[nb][lkc + 3][lrow] = a_pre.w;
#pragma unroll
            for (int q = 0; q < 4; q++)
                *reinterpret_cast<float4*>(&sB[nb][lkb][lc16 + q * 4]) = b_pre[q];
        }
        __syncthreads();
        buf ^= 1;
    }

    float b0 = bout[tx * 4 + 0], b1 = bout[tx * 4 + 1], b2 = bout[tx * 4 + 2], b3 = bout[tx * 4 + 3];
    float g0 = gamma[tx * 4 + 0], g1 = gamma[tx * 4 + 1], g2 = gamma[tx * 4 + 2], g3 = gamma[tx * 4 + 3];
    float be0 = beta[tx * 4 + 0], be1 = beta[tx * 4 + 1], be2 = beta[tx * 4 + 2], be3 = beta[tx * 4 + 3];
#pragma unroll
    for (int i = 0; i < 4; i++) {
        int r = bm + ty * 4 + i;
        float v[4];
        unpackf(acc[i][0], v[0], v[1]);
        unpackf(acc[i][1], v[2], v[3]);
        v[0] += b0; v[1] += b1; v[2] += b2; v[3] += b3;
        float psum = v[0] + v[1] + v[2] + v[3];
#pragma unroll
        for (int o = 16; o; o >>= 1) psum += __shfl_xor_sync(0xffffffffu, psum, o);
        float mu = psum * (1.f / OUT_DIMC);
        float d0 = v[0] - mu, d1 = v[1] - mu, d2 = v[2] - mu, d3 = v[3] - mu;
        float pss = d0 * d0 + d1 * d1 + d2 * d2 + d3 * d3;
#pragma unroll
        for (int o = 16; o; o >>= 1) pss += __shfl_xor_sync(0xffffffffu, pss, o);
        float inv = rsqrtf(pss * (1.f / OUT_DIMC) + LN_EPSF);
        if (r < NN) {
            float4 res = make_float4(d0 * inv * g0 + be0, d1 * inv * g1 + be1,
                                     d2 * inv * g2 + be2, d3 * inv * g3 + be3);
            *reinterpret_cast<float4*>(out + (size_t)r * OUT_DIMC + tx * 4) = res;
        }
    }
}

// ---------------- launch ----------------
extern "C" void kernel_launch(void* const* d_in, const int* in_sizes, int n_in,
                              void* d_out, int out_size) {
    const float* x     = (const float*)d_in[0];
    const int*   ei    = (const int*)d_in[1];
    const float* W_in  = (const float*)d_in[2];
    const float* b_in  = (const float*)d_in[3];
    const float* lin0  = (const float*)d_in[4];
    const float* att0s = (const float*)d_in[5];
    const float* att0d = (const float*)d_in[6];
    const float* bias0 = (const float*)d_in[7];
    const float* lin1  = (const float*)d_in[8];
    const float* att1s = (const float*)d_in[9];
    const float* att1d = (const float*)d_in[10];
    const float* bias1 = (const float*)d_in[11];
    const float* Wout  = (const float*)d_in[12];
    const float* bout  = (const float*)d_in[13];
    const float* gamma = (const float*)d_in[14];
    const float* beta  = (const float*)d_in[15];
    float* out = (float*)d_out;

    int E = in_sizes[1] / 2;
    if (E > EE) E = EE;
    const int* srcp = ei;
    const int* dstp = ei + E;

    float *h0p = nullptr, *featp = nullptr, *aggp = nullptr;
    cudaGetSymbolAddress((void**)&h0p, g_h0);
    cudaGetSymbolAddress((void**)&featp, g_feat);
    cudaGetSymbolAddress((void**)&aggp, g_agg);

    const int nsb = (NN + 255) / 256;
    const int gxa = (NN + TBM - 1) / TBM;
    const int gagg = (NN + AGG_WARPS * 2 - 1) / (AGG_WARPS * 2);

    // fork a side stream for the graph build so it overlaps the first GEMMs
    cudaStream_t s2;
    cudaStreamCreateWithFlags(&s2, cudaStreamNonBlocking);
    cudaEvent_t e0, e1;
    cudaEventCreateWithFlags(&e0, cudaEventDisableTiming);
    cudaEventCreateWithFlags(&e1, cudaEventDisableTiming);

    cudaEventRecord(e0, 0);
    cudaStreamWaitEvent(s2, e0, 0);

    zero_deg_kernel<<<nsb, 256, 0, s2>>>();
    count_deg_kernel<<<(E + 255) / 256, 256, 0, s2>>>(dstp, E);

    gemm_kernel<<<dim3((NN + BM - 1) / BM, HIDC / BN), 256>>>(
        x, W_in, b_in, h0p, NN, HIDC, IN_DIMC, 1);
    gemm_att_kernel<<<dim3(gxa, 2), 256>>>(h0p, lin0, featp, att0s, att0d, NN, HIDC);

    scan_p1_kernel<<<nsb, 256, 0, s2>>>();
    scan_p2_kernel<<<1, 256, 0, s2>>>(nsb);
    scan_p3_kernel<<<nsb, 256, 0, s2>>>();
    scatter_kernel<<<(E + 255) / 256, 256, 0, s2>>>(srcp, dstp, E);
    cudaEventRecord(e1, s2);
    cudaStreamWaitEvent(0, e1, 0);

    gat_fused_kernel<<<gagg, AGG_WARPS * 32>>>(featp, bias0, aggp);

    gemm_att_kernel<<<dim3(gxa, 2), 256>>>(aggp, lin1, featp, att1s, att1d, NN, HCC);
    gat_fused_kernel<<<gagg, AGG_WARPS * 32>>>(featp, bias1, aggp);

    onl_kernel<<<(NN + ONB - 1) / ONB, 256>>>(aggp, Wout, bout, gamma, beta, out);
}

// round 15
// speedup vs baseline: 1.0428x; 1.0428x over previous
#include <cuda_runtime.h>
#include <math.h>

#define NN 50000
#define EE 800000
#define IN_DIMC 32
#define HIDC 64
#define HEADSC 4
#define HCC 256
#define OUT_DIMC 128
#define LN_EPSF 1e-5f
#define NEG_SLOPEF 0.2f

typedef unsigned long long ull;

// ---------------- scratch (device globals; no allocation allowed) ----------------
__device__ float g_h0[NN * HIDC];
__device__ float g_feat[NN * HCC];
__device__ float g_agg[NN * HCC];
__device__ float g_asrc[NN * HEADSC];
__device__ float g_adst[NN * HEADSC];
__device__ int   g_deg[NN];
__device__ int   g_off[NN + 1];
__device__ int   g_cur[NN];
__device__ int   g_srclist[EE];
__device__ int   g_bsum[256];

__device__ __forceinline__ float eluf(float x) { return x > 0.f ? x : expm1f(x); }
__device__ __forceinline__ float lrelu(float x) { return x > 0.f ? x : NEG_SLOPEF * x; }

__device__ __forceinline__ void fma2(ull& d, ull a, ull b) {
    asm("fma.rn.f32x2 %0, %1, %2, %0;" : "+l"(d) : "l"(a), "l"(b));
}
__device__ __forceinline__ ull dupf(float a) {
    ull r;
    asm("mov.b64 %0, {%1, %1};" : "=l"(r) : "f"(a));
    return r;
}
__device__ __forceinline__ ull packf(float a, float b) {
    ull r;
    asm("mov.b64 %0, {%1, %2};" : "=l"(r) : "f"(a), "f"(b));
    return r;
}
__device__ __forceinline__ void unpackf(ull v, float& lo, float& hi) {
    asm("mov.b64 {%0, %1}, %2;" : "=f"(lo), "=f"(hi) : "l"(v));
}
__device__ __forceinline__ void cpasync16(unsigned smem_addr, const void* gptr) {
    asm volatile("cp.async.cg.shared.global [%0], [%1], 16;" :: "r"(smem_addr), "l"(gptr));
}
__device__ __forceinline__ unsigned smem_u32(const void* p) {
    return (unsigned)__cvta_generic_to_shared(p);
}

// ---------------- graph build ----------------
__global__ void zero_deg_kernel() {
    int i = blockIdx.x * blockDim.x + threadIdx.x;
    if (i < NN) g_deg[i] = 0;
}

__global__ void count_deg_kernel(const int* __restrict__ dst, int E) {
    int i = blockIdx.x * blockDim.x + threadIdx.x;
    if (i < E) atomicAdd(&g_deg[dst[i]], 1);
}

__global__ void scan_p1_kernel() {
    __shared__ int s[256];
    int t = threadIdx.x;
    int i = blockIdx.x * 256 + t;
    int v = (i < NN) ? g_deg[i] : 0;
    s[t] = v;
    __syncthreads();
#pragma unroll
    for (int d = 1; d < 256; d <<= 1) {
        int u = (t >= d) ? s[t - d] : 0;
        __syncthreads();
        s[t] += u;
        __syncthreads();
    }
    if (i < NN) g_off[i] = s[t] - v;
    if (t == 255) g_bsum[blockIdx.x] = s[255];
}

__global__ void scan_p2_kernel(int nblocks) {
    __shared__ int s[256];
    int t = threadIdx.x;
    int v = (t < nblocks) ? g_bsum[t] : 0;
    s[t] = v;
    __syncthreads();
#pragma unroll
    for (int d = 1; d < 256; d <<= 1) {
        int u = (t >= d) ? s[t - d] : 0;
        __syncthreads();
        s[t] += u;
        __syncthreads();
    }
    if (t < nblocks) g_bsum[t] = s[t] - v;
}

__global__ void scan_p3_kernel() {
    int i = blockIdx.x * 256 + threadIdx.x;
    if (i < NN) {
        int o = g_off[i] + g_bsum[blockIdx.x];
        g_off[i] = o;
        g_cur[i] = o;
        if (i == NN - 1) g_off[NN] = o + g_deg[i];
    }
}

__global__ void scatter_kernel(const int* __restrict__ src, const int* __restrict__ dst, int E) {
    int i = blockIdx.x * blockDim.x + threadIdx.x;
    if (i < E) {
        int p = atomicAdd(&g_cur[dst[i]], 1);
        g_srclist[p] = src[i];
    }
}

// ---------------- small SGEMM (input projection, N=64) ----------------
#define BM 64
#define BN 64
#define BK 16
__global__ void gemm_kernel(const float* __restrict__ A, const float* __restrict__ B,
                            const float* __restrict__ bias, float* __restrict__ C,
                            int M, int Ncol, int K, int act) {
    __shared__ float sA[BK][BM];
    __shared__ float sB[BK][BN];
    int tid = threadIdx.x;
    int bm = blockIdx.x * BM, bn = blockIdx.y * BN;
    int ty = tid / 16, tx = tid % 16;
    float acc[4][4] = {};
    int arow = tid >> 2;
    int akc  = (tid & 3) * 4;
    int brow = tid >> 4;
    int bcol = (tid & 15) * 4;

    for (int k0 = 0; k0 < K; k0 += BK) {
        float4 av = make_float4(0.f, 0.f, 0.f, 0.f);
        int gr = bm + arow;
        if (gr < M) av = *reinterpret_cast<const float4*>(A + (size_t)gr * K + k0 + akc);
        sA[akc + 0][arow] = av.x;
        sA[akc + 1][arow] = av.y;
        sA[akc + 2][arow] = av.z;
        sA[akc + 3][arow] = av.w;
        float4 bv = *reinterpret_cast<const float4*>(B + (size_t)(k0 + brow) * Ncol + bn + bcol);
        *reinterpret_cast<float4*>(&sB[brow][bcol]) = bv;
        __syncthreads();
#pragma unroll
        for (int k = 0; k < BK; k++) {
            float4 a4 = *reinterpret_cast<const float4*>(&sA[k][ty * 4]);
            float4 b4 = *reinterpret_cast<const float4*>(&sB[k][tx * 4]);
            float a[4] = {a4.x, a4.y, a4.z, a4.w};
            float b[4] = {b4.x, b4.y, b4.z, b4.w};
#pragma unroll
            for (int i = 0; i < 4; i++)
#pragma unroll
                for (int j = 0; j < 4; j++) acc[i][j] = fmaf(a[i], b[j], acc[i][j]);
        }
        __syncthreads();
    }
#pragma unroll
    for (int i = 0; i < 4; i++) {
        int r = bm + ty * 4 + i;
        if (r >= M) break;
#pragma unroll
        for (int j = 0; j < 4; j++) {
            int c = bn + tx * 4 + j;
            float v = acc[i][j];
            if (bias) v += bias[c];
            if (act) v = eluf(v);
            C[(size_t)r * Ncol + c] = v;
        }
    }
}

// ---------------- 96x128 SGEMM + attention epilogue (3 CTAs/SM, 3-stage cp.async) ----------------
#define TBM 96
#define TBN 128
#define TBK 16
#define TAPAD 100   // 400B row stride, 16B aligned

__global__ __launch_bounds__(256, 3) void gemm_att_kernel(
    const float* __restrict__ A, const float* __restrict__ B,
    float* __restrict__ C, const float* __restrict__ att_src,
    const float* __restrict__ att_dst, int M, int K) {
    __shared__ float sA[2][TBK][TAPAD];
    __shared__ float sB[3][TBK][TBN];
    __shared__ float s_as[TBN];
    __shared__ float s_ad[TBN];

    int tid = threadIdx.x;        // 256
    int bm = blockIdx.x * TBM;
    int bn = blockIdx.y * TBN;    // 0 or 128
    int w = tid >> 5;             // warp 0..7 -> rows 12w..12w+11
    int tx = tid & 31;            // cols bn + tx*4..+3

    if (tid < TBN) {
        s_as[tid] = att_src[bn + tid];
        s_ad[tid] = att_dst[bn + tid];
    }

    int arow = tid >> 1;          // 0..95 (valid when tid<192)
    int akc  = (tid & 1) * 8;     // 0 or 8
    bool aload = (tid < 192);
    int gr = bm + arow;
    bool avalid = aload && (gr < M);
    const float* Arow = A + (size_t)gr * K + akc;

    int lkb  = tid >> 4;          // 0..15
    int bcol = (tid & 15) * 8;    // 0..120
    const float* Bbase = B + (size_t)lkb * HCC + bn + bcol;

    ull acc[6][4];
#pragma unroll
    for (int p = 0; p < 6; p++)
#pragma unroll
        for (int j = 0; j < 4; j++) acc[p][j] = 0ull;

    const int T = K / TBK;

    float4 av0 = make_float4(0.f, 0.f, 0.f, 0.f);
    float4 av1 = make_float4(0.f, 0.f, 0.f, 0.f);
    if (avalid) {
        av0 = *reinterpret_cast<const float4*>(Arow);
        av1 = *reinterpret_cast<const float4*>(Arow + 4);
    }
    {
        unsigned d0 = smem_u32(&sB[0][lkb][bcol]);
        cpasync16(d0, Bbase);
        cpasync16(d0 + 16, Bbase + 4);
        asm volatile("cp.async.commit_group;");
        if (T > 1) {
            unsigned d1 = smem_u32(&sB[1][lkb][bcol]);
            const float* g1 = Bbase + (size_t)TBK * HCC;
            cpasync16(d1, g1);
            cpasync16(d1 + 16, g1 + 4);
            asm volatile("cp.async.commit_group;");
        }
    }

    int st = 0;
    int ab = 0;
    for (int t = 0; t < T; t++) {
        if (t + 1 < T) asm volatile("cp.async.wait_group 1;");
        else           asm volatile("cp.async.wait_group 0;");
        if (aload) {
            sA[ab][akc + 0][arow] = av0.x;
            sA[ab][akc + 1][arow] = av0.y;
            sA[ab][akc + 2][arow] = av0.z;
            sA[ab][akc + 3][arow] = av0.w;
            sA[ab][akc + 4][arow] = av1.x;
            sA[ab][akc + 5][arow] = av1.y;
            sA[ab][akc + 6][arow] = av1.z;
            sA[ab][akc + 7][arow] = av1.w;
        }
        __syncthreads();
        // issue B(t+2) EARLY: slot (st+2)%3 was last read during compute(t-1),
        // which every warp finished before the barrier above.
        if (t + 2 < T) {
            int ns = (st + 2 >= 3) ? st - 1 : st + 2;
            unsigned dn = smem_u32(&sB[ns][lkb][bcol]);
            const float* gn = Bbase + (size_t)(t + 2) * TBK * HCC;
            cpasync16(dn, gn);
            cpasync16(dn + 16, gn + 4);
        }
        asm volatile("cp.async.commit_group;");
        // prefetch A(t+1) into registers
        if (t + 1 < T && avalid) {
            av0 = *reinterpret_cast<const float4*>(Arow + (size_t)(t + 1) * TBK);
            av1 = *reinterpret_cast<const float4*>(Arow + (size_t)(t + 1) * TBK + 4);
        }
#pragma unroll
        for (int k = 0; k < TBK; k++) {
            longlong2 a01 = *reinterpret_cast<const longlong2*>(&sA[ab][k][w * 12]);
            longlong2 a23 = *reinterpret_cast<const longlong2*>(&sA[ab][k][w * 12 + 4]);
            longlong2 a45 = *reinterpret_cast<const longlong2*>(&sA[ab][k][w * 12 + 8]);
            float4 b4 = *reinterpret_cast<const float4*>(&sB[st][k][tx * 4]);
            ull ap[6] = {(ull)a01.x, (ull)a01.y, (ull)a23.x, (ull)a23.y, (ull)a45.x, (ull)a45.y};
            float b[4] = {b4.x, b4.y, b4.z, b4.w};
#pragma unroll
            for (int j = 0; j < 4; j++) {
                ull bd = dupf(b[j]);
#pragma unroll
                for (int p = 0; p < 6; p++) fma2(acc[p][j], ap[p], bd);
            }
        }
        st = (st + 1 == 3) ? 0 : st + 1;
        ab ^= 1;
    }

    int h = (bn >> 6) + (tx >> 4);
    float ws[4], wd[4];
#pragma unroll
    for (int q = 0; q < 4; q++) {
        ws[q] = s_as[tx * 4 + q];
        wd[q] = s_ad[tx * 4 + q];
    }

#pragma unroll
    for (int p = 0; p < 6; p++) {
#pragma unroll
        for (int half = 0; half < 2; half++) {
            int r = bm + w * 12 + 2 * p + half;
            float v[4];
            {
                float l0, h0, l1, h1, l2, h2, l3, h3;
                unpackf(acc[p][0], l0, h0);
                unpackf(acc[p][1], l1, h1);
                unpackf(acc[p][2], l2, h2);
                unpackf(acc[p][3], l3, h3);
                v[0] = half ? h0 : l0;
                v[1] = half ? h1 : l1;
                v[2] = half ? h2 : l2;
                v[3] = half ? h3 : l3;
            }
            float p1 = v[0] * ws[0] + v[1] * ws[1] + v[2] * ws[2] + v[3] * ws[3];
            float p2 = v[0] * wd[0] + v[1] * wd[1] + v[2] * wd[2] + v[3] * wd[3];
#pragma unroll
            for (int o = 8; o; o >>= 1) {
                p1 += __shfl_xor_sync(0xffffffffu, p1, o);
                p2 += __shfl_xor_sync(0xffffffffu, p2, o);
            }
            if (r < M) {
                if ((tx & 15) == 0) {
                    g_asrc[(size_t)r * HEADSC + h] = p1;
                    g_adst[(size_t)r * HEADSC + h] = p2;
                }
                *reinterpret_cast<float4*>(C + (size_t)r * HCC + bn + tx * 4) =
                    make_float4(v[0], v[1], v[2], v[3]);
            }
        }
    }
}

// ---------------- single-pass warp-per-dst GAT aggregation (measured optimum) ----------------
#define AGG_WARPS 8
__global__ __launch_bounds__(AGG_WARPS * 32) void gat_fused_kernel(
    const float* __restrict__ feat, const float* __restrict__ bias,
    float* __restrict__ out) {
    __shared__ float s_p[AGG_WARPS][32][HEADSC];
    __shared__ int s_src[AGG_WARPS][32];

    int wid = threadIdx.x >> 5;
    int lane = threadIdx.x & 31;
    int d = blockIdx.x * AGG_WARPS + wid;
    if (d >= NN) return;

    int base = g_off[d];
    int deg = g_off[d + 1] - base;
    int total = deg + 1;

    float4 ad4 = *reinterpret_cast<const float4*>(g_adst + (size_t)d * HEADSC);
    float adst[4] = {ad4.x, ad4.y, ad4.z, ad4.w};

    int myc = lane * 8;
    int myh = lane >> 3;
    float acc[8] = {0.f, 0.f, 0.f, 0.f, 0.f, 0.f, 0.f, 0.f};
    float denh[4] = {0.f, 0.f, 0.f, 0.f};

    for (int ch = 0; ch < total; ch += 32) {
        int j = ch + lane;
        if (j < total) {
            int s = (j < deg) ? g_srclist[base + j] : d;
            float4 as4 = *reinterpret_cast<const float4*>(g_asrc + (size_t)s * HEADSC);
            float p0 = __expf(lrelu(as4.x + adst[0]));
            float p1 = __expf(lrelu(as4.y + adst[1]));
            float p2 = __expf(lrelu(as4.z + adst[2]));
            float p3 = __expf(lrelu(as4.w + adst[3]));
            denh[0] += p0; denh[1] += p1; denh[2] += p2; denh[3] += p3;
            s_p[wid][lane][0] = p0;
            s_p[wid][lane][1] = p1;
            s_p[wid][lane][2] = p2;
            s_p[wid][lane][3] = p3;
            s_src[wid][lane] = s;
        }
        __syncwarp();
        int lim = min(32, total - ch);
        int jj = 0;
        for (; jj + 2 <= lim; jj += 2) {
            int s0 = s_src[wid][jj];
            int s1 = s_src[wid][jj + 1];
            float a0 = s_p[wid][jj][myh];
            float a1 = s_p[wid][jj + 1][myh];
            float4 f00 = *reinterpret_cast<const float4*>(feat + (size_t)s0 * HCC + myc);
            float4 f01 = *reinterpret_cast<const float4*>(feat + (size_t)s0 * HCC + myc + 4);
            float4 f10 = *reinterpret_cast<const float4*>(feat + (size_t)s1 * HCC + myc);
            float4 f11 = *reinterpret_cast<const float4*>(feat + (size_t)s1 * HCC + myc + 4);
            acc[0] = fmaf(a0, f00.x, acc[0]); acc[1] = fmaf(a0, f00.y, acc[1]);
            acc[2] = fmaf(a0, f00.z, acc[2]); acc[3] = fmaf(a0, f00.w, acc[3]);
            acc[4] = fmaf(a0, f01.x, acc[4]); acc[5] = fmaf(a0, f01.y, acc[5]);
            acc[6] = fmaf(a0, f01.z, acc[6]); acc[7] = fmaf(a0, f01.w, acc[7]);
            acc[0] = fmaf(a1, f10.x, acc[0]); acc[1] = fmaf(a1, f10.y, acc[1]);
            acc[2] = fmaf(a1, f10.z, acc[2]); acc[3] = fmaf(a1, f10.w, acc[3]);
            acc[4] = fmaf(a1, f11.x, acc[4]); acc[5] = fmaf(a1, f11.y, acc[5]);
            acc[6] = fmaf(a1, f11.z, acc[6]); acc[7] = fmaf(a1, f11.w, acc[7]);
        }
        for (; jj < lim; jj++) {
            int s0 = s_src[wid][jj];
            float a0 = s_p[wid][jj][myh];
            float4 f00 = *reinterpret_cast<const float4*>(feat + (size_t)s0 * HCC + myc);
            float4 f01 = *reinterpret_cast<const float4*>(feat + (size_t)s0 * HCC + myc + 4);
            acc[0] = fmaf(a0, f00.x, acc[0]); acc[1] = fmaf(a0, f00.y, acc[1]);
            acc[2] = fmaf(a0, f00.z, acc[2]); acc[3] = fmaf(a0, f00.w, acc[3]);
            acc[4] = fmaf(a0, f01.x, acc[4]); acc[5] = fmaf(a0, f01.y, acc[5]);
            acc[6] = fmaf(a0, f01.z, acc[6]); acc[7] = fmaf(a0, f01.w, acc[7]);
        }
        __syncwarp();
    }

#pragma unroll
    for (int o = 16; o; o >>= 1) {
#pragma unroll
        for (int h = 0; h < 4; h++) denh[h] += __shfl_xor_sync(0xffffffffu, denh[h], o);
    }
    float inv = 1.f / (denh[myh] + 1e-16f);

    float* orow = out + (size_t)d * HCC + myc;
    const float* brow = bias + myc;
    float4 b0 = *reinterpret_cast<const float4*>(brow);
    float4 b1 = *reinterpret_cast<const float4*>(brow + 4);
    float4 r0 = make_float4(eluf(acc[0] * inv + b0.x), eluf(acc[1] * inv + b0.y),
                            eluf(acc[2] * inv + b0.z), eluf(acc[3] * inv + b0.w));
    float4 r1 = make_float4(eluf(acc[4] * inv + b1.x), eluf(acc[5] * inv + b1.y),
                            eluf(acc[6] * inv + b1.z), eluf(acc[7] * inv + b1.w));
    *reinterpret_cast<float4*>(orow) = r0;
    *reinterpret_cast<float4*>(orow + 4) = r1;
}

// ---------------- fused out projection + layernorm, double-buffered ----------------
#define ONB 32
__global__ __launch_bounds__(256) void onl_kernel(
    const float* __restrict__ hin, const float* __restrict__ Wout,
    const float* __restrict__ bout, const float* __restrict__ gamma,
    const float* __restrict__ beta, float* __restrict__ out) {
    __shared__ float sA[2][32][ONB + 1];
    __shared__ float sB[2][32][OUT_DIMC];
    int tid = threadIdx.x;  // 256
    int bm = blockIdx.x * ONB;
    int ty = tid >> 5;
    int tx = tid & 31;

    int lrow = tid >> 3;
    int lkc  = (tid & 7) * 4;
    int lkb  = tid >> 3;
    int lc16 = (tid & 7) * 16;

    ull acc[4][2];
#pragma unroll
    for (int i = 0; i < 4; i++) { acc[i][0] = 0ull; acc[i][1] = 0ull; }

    const int T = HCC / 32;  // 8
    int gr = bm + lrow;
    float4 a_pre = (gr < NN) ? *reinterpret_cast<const float4*>(hin + (size_t)gr * HCC + lkc)
                             : make_float4(0.f, 0.f, 0.f, 0.f);
    float4 b_pre[4];
#pragma unroll
    for (int q = 0; q < 4; q++)
        b_pre[q] = *reinterpret_cast<const float4*>(Wout + (size_t)lkb * OUT_DIMC + lc16 + q * 4);

    sA[0][lkc + 0][lrow] = a_pre.x;
    sA[0][lkc + 1][lrow] = a_pre.y;
    sA[0][lkc + 2][lrow] = a_pre.z;
    sA[0][lkc + 3][lrow] = a_pre.w;
#pragma unroll
    for (int q = 0; q < 4; q++)
        *reinterpret_cast<float4*>(&sB[0][lkb][lc16 + q * 4]) = b_pre[q];
    __syncthreads();

    int buf = 0;
    for (int t = 0; t < T; t++) {
        if (t + 1 < T) {
            int k0 = (t + 1) * 32;
            a_pre = (gr < NN) ? *reinterpret_cast<const float4*>(hin + (size_t)gr * HCC + k0 + lkc)
                              : make_float4(0.f, 0.f, 0.f, 0.f);
#pragma unroll
            for (int q = 0; q < 4; q++)
                b_pre[q] = *reinterpret_cast<const float4*>(Wout + (size_t)(k0 + lkb) * OUT_DIMC + lc16 + q * 4);
        }
#pragma unroll 8
        for (int k = 0; k < 32; k++) {
            float4 b4 = *reinterpret_cast<const float4*>(&sB[buf][k][tx * 4]);
            ull bp0 = packf(b4.x, b4.y);
            ull bp1 = packf(b4.z, b4.w);
#pragma unroll
            for (int i = 0; i < 4; i++) {
                ull ad = dupf(sA[buf][k][ty * 4 + i]);
                fma2(acc[i][0], ad, bp0);
                fma2(acc[i][1], ad, bp1);
            }
        }
        if (t + 1 < T) {
            int nb = buf ^ 1;
            sA[nb][lkc + 0][lrow] = a_pre.x;
            sA[nb][lkc + 1][lrow] = a_pre.y;
            sA[nb][lkc + 2][lrow] = a_pre.z;
            sA[nb][lkc + 3][lrow] = a_pre.w;
#pragma unroll
            for (int q = 0; q < 4; q++)
                *reinterpret_cast<float4*>(&sB[nb][lkb][lc16 + q * 4]) = b_pre[q];
        }
        __syncthreads();
        buf ^= 1;
    }

    float b0 = bout[tx * 4 + 0], b1 = bout[tx * 4 + 1], b2 = bout[tx * 4 + 2], b3 = bout[tx * 4 + 3];
    float g0 = gamma[tx * 4 + 0], g1 = gamma[tx * 4 + 1], g2 = gamma[tx * 4 + 2], g3 = gamma[tx * 4 + 3];
    float be0 = beta[tx * 4 + 0], be1 = beta[tx * 4 + 1], be2 = beta[tx * 4 + 2], be3 = beta[tx * 4 + 3];
#pragma unroll
    for (int i = 0; i < 4; i++) {
        int r = bm + ty * 4 + i;
        float v[4];
        unpackf(acc[i][0], v[0], v[1]);
        unpackf(acc[i][1], v[2], v[3]);
        v[0] += b0; v[1] += b1; v[2] += b2; v[3] += b3;
        float psum = v[0] + v[1] + v[2] + v[3];
#pragma unroll
        for (int o = 16; o; o >>= 1) psum += __shfl_xor_sync(0xffffffffu, psum, o);
        float mu = psum * (1.f / OUT_DIMC);
        float d0 = v[0] - mu, d1 = v[1] - mu, d2 = v[2] - mu, d3 = v[3] - mu;
        float pss = d0 * d0 + d1 * d1 + d2 * d2 + d3 * d3;
#pragma unroll
        for (int o = 16; o; o >>= 1) pss += __shfl_xor_sync(0xffffffffu, pss, o);
        float inv = rsqrtf(pss * (1.f / OUT_DIMC) + LN_EPSF);
        if (r < NN) {
            float4 res = make_float4(d0 * inv * g0 + be0, d1 * inv * g1 + be1,
                                     d2 * inv * g2 + be2, d3 * inv * g3 + be3);
            *reinterpret_cast<float4*>(out + (size_t)r * OUT_DIMC + tx * 4) = res;
        }
    }
}

// ---------------- launch ----------------
extern "C" void kernel_launch(void* const* d_in, const int* in_sizes, int n_in,
                              void* d_out, int out_size) {
    const float* x     = (const float*)d_in[0];
    const int*   ei    = (const int*)d_in[1];
    const float* W_in  = (const float*)d_in[2];
    const float* b_in  = (const float*)d_in[3];
    const float* lin0  = (const float*)d_in[4];
    const float* att0s = (const float*)d_in[5];
    const float* att0d = (const float*)d_in[6];
    const float* bias0 = (const float*)d_in[7];
    const float* lin1  = (const float*)d_in[8];
    const float* att1s = (const float*)d_in[9];
    const float* att1d = (const float*)d_in[10];
    const float* bias1 = (const float*)d_in[11];
    const float* Wout  = (const float*)d_in[12];
    const float* bout  = (const float*)d_in[13];
    const float* gamma = (const float*)d_in[14];
    const float* beta  = (const float*)d_in[15];
    float* out = (float*)d_out;

    int E = in_sizes[1] / 2;
    if (E > EE) E = EE;
    const int* srcp = ei;
    const int* dstp = ei + E;

    float *h0p = nullptr, *featp = nullptr, *aggp = nullptr;
    cudaGetSymbolAddress((void**)&h0p, g_h0);
    cudaGetSymbolAddress((void**)&featp, g_feat);
    cudaGetSymbolAddress((void**)&aggp, g_agg);

    const int nsb = (NN + 255) / 256;
    const int gxa = (NN + TBM - 1) / TBM;
    const int gagg = (NN + AGG_WARPS - 1) / AGG_WARPS;

    // fork a side stream for the graph build so it overlaps the first GEMMs
    cudaStream_t s2;
    cudaStreamCreateWithFlags(&s2, cudaStreamNonBlocking);
    cudaEvent_t e0, e1;
    cudaEventCreateWithFlags(&e0, cudaEventDisableTiming);
    cudaEventCreateWithFlags(&e1, cudaEventDisableTiming);

    cudaEventRecord(e0, 0);
    cudaStreamWaitEvent(s2, e0, 0);

    zero_deg_kernel<<<nsb, 256, 0, s2>>>();
    count_deg_kernel<<<(E + 255) / 256, 256, 0, s2>>>(dstp, E);

    gemm_kernel<<<dim3((NN + BM - 1) / BM, HIDC / BN), 256>>>(
        x, W_in, b_in, h0p, NN, HIDC, IN_DIMC, 1);
    gemm_att_kernel<<<dim3(gxa, 2), 256>>>(h0p, lin0, featp, att0s, att0d, NN, HIDC);

    scan_p1_kernel<<<nsb, 256, 0, s2>>>();
    scan_p2_kernel<<<1, 256, 0, s2>>>(nsb);
    scan_p3_kernel<<<nsb, 256, 0, s2>>>();
    scatter_kernel<<<(E + 255) / 256, 256, 0, s2>>>(srcp, dstp, E);
    cudaEventRecord(e1, s2);
    cudaStreamWaitEvent(0, e1, 0);

    gat_fused_kernel<<<gagg, AGG_WARPS * 32>>>(featp, bias0, aggp);

    gemm_att_kernel<<<dim3(gxa, 2), 256>>>(aggp, lin1, featp, att1s, att1d, NN, HCC);
    gat_fused_kernel<<<gagg, AGG_WARPS * 32>>>(featp, bias1, aggp);

    onl_kernel<<<(NN + ONB - 1) / ONB, 256>>>(aggp, Wout, bout, gamma, beta, out);
}

// round 17
// speedup vs baseline: 1.0428x; 1.0001x over previous
#include <cuda_runtime.h>
#include <math.h>

#define NN 50000
#define EE 800000
#define IN_DIMC 32
#define HIDC 64
#define HEADSC 4
#define HCC 256
#define OUT_DIMC 128
#define LN_EPSF 1e-5f
#define NEG_SLOPEF 0.2f

typedef unsigned long long ull;

// ---------------- scratch (device globals; no allocation allowed) ----------------
__device__ float g_h0[NN * HIDC];
__device__ float g_feat[NN * HCC];
__device__ float g_agg[NN * HCC];
__device__ float g_asrc[NN * HEADSC];
__device__ float g_adst[NN * HEADSC];
__device__ int   g_deg[NN];
__device__ int   g_off[NN + 1];
__device__ int   g_cur[NN];
__device__ int   g_srclist[EE];
__device__ int   g_bsum[256];

__device__ __forceinline__ float eluf(float x) { return x > 0.f ? x : expm1f(x); }
__device__ __forceinline__ float lrelu(float x) { return x > 0.f ? x : NEG_SLOPEF * x; }

__device__ __forceinline__ void fma2(ull& d, ull a, ull b) {
    asm("fma.rn.f32x2 %0, %1, %2, %0;" : "+l"(d) : "l"(a), "l"(b));
}
__device__ __forceinline__ ull dupf(float a) {
    ull r;
    asm("mov.b64 %0, {%1, %1};" : "=l"(r) : "f"(a));
    return r;
}
__device__ __forceinline__ ull packf(float a, float b) {
    ull r;
    asm("mov.b64 %0, {%1, %2};" : "=l"(r) : "f"(a), "f"(b));
    return r;
}
__device__ __forceinline__ void unpackf(ull v, float& lo, float& hi) {
    asm("mov.b64 {%0, %1}, %2;" : "=f"(lo), "=f"(hi) : "l"(v));
}
__device__ __forceinline__ void cpasync16(unsigned smem_addr, const void* gptr) {
    asm volatile("cp.async.cg.shared.global [%0], [%1], 16;" :: "r"(smem_addr), "l"(gptr));
}
__device__ __forceinline__ unsigned smem_u32(const void* p) {
    return (unsigned)__cvta_generic_to_shared(p);
}

// ---------------- graph build ----------------
__global__ void zero_deg_kernel() {
    int i = blockIdx.x * blockDim.x + threadIdx.x;
    if (i < NN) g_deg[i] = 0;
}

__global__ void count_deg_kernel(const int* __restrict__ dst, int E) {
    int i = blockIdx.x * blockDim.x + threadIdx.x;
    if (i < E) atomicAdd(&g_deg[dst[i]], 1);
}

__global__ void scan_p1_kernel() {
    __shared__ int s[256];
    int t = threadIdx.x;
    int i = blockIdx.x * 256 + t;
    int v = (i < NN) ? g_deg[i] : 0;
    s[t] = v;
    __syncthreads();
#pragma unroll
    for (int d = 1; d < 256; d <<= 1) {
        int u = (t >= d) ? s[t - d] : 0;
        __syncthreads();
        s[t] += u;
        __syncthreads();
    }
    if (i < NN) g_off[i] = s[t] - v;
    if (t == 255) g_bsum[blockIdx.x] = s[255];
}

__global__ void scan_p2_kernel(int nblocks) {
    __shared__ int s[256];
    int t = threadIdx.x;
    int v = (t < nblocks) ? g_bsum[t] : 0;
    s[t] = v;
    __syncthreads();
#pragma unroll
    for (int d = 1; d < 256; d <<= 1) {
        int u = (t >= d) ? s[t - d] : 0;
        __syncthreads();
        s[t] += u;
        __syncthreads();
    }
    if (t < nblocks) g_bsum[t] = s[t] - v;
}

__global__ void scan_p3_kernel() {
    int i = blockIdx.x * 256 + threadIdx.x;
    if (i < NN) {
        int o = g_off[i] + g_bsum[blockIdx.x];
        g_off[i] = o;
        g_cur[i] = o;
        if (i == NN - 1) g_off[NN] = o + g_deg[i];
    }
}

__global__ void scatter_kernel(const int* __restrict__ src, const int* __restrict__ dst, int E) {
    int i = blockIdx.x * blockDim.x + threadIdx.x;
    if (i < E) {
        int p = atomicAdd(&g_cur[dst[i]], 1);
        g_srclist[p] = src[i];
    }
}

// ---------------- small SGEMM (input projection, N=64) ----------------
#define BM 64
#define BN 64
#define BK 16
__global__ void gemm_kernel(const float* __restrict__ A, const float* __restrict__ B,
                            const float* __restrict__ bias, float* __restrict__ C,
                            int M, int Ncol, int K, int act) {
    __shared__ float sA[BK][BM];
    __shared__ float sB[BK][BN];
    int tid = threadIdx.x;
    int bm = blockIdx.x * BM, bn = blockIdx.y * BN;
    int ty = tid / 16, tx = tid % 16;
    float acc[4][4] = {};
    int arow = tid >> 2;
    int akc  = (tid & 3) * 4;
    int brow = tid >> 4;
    int bcol = (tid & 15) * 4;

    for (int k0 = 0; k0 < K; k0 += BK) {
        float4 av = make_float4(0.f, 0.f, 0.f, 0.f);
        int gr = bm + arow;
        if (gr < M) av = *reinterpret_cast<const float4*>(A + (size_t)gr * K + k0 + akc);
        sA[akc + 0][arow] = av.x;
        sA[akc + 1][arow] = av.y;
        sA[akc + 2][arow] = av.z;
        sA[akc + 3][arow] = av.w;
        float4 bv = *reinterpret_cast<const float4*>(B + (size_t)(k0 + brow) * Ncol + bn + bcol);
        *reinterpret_cast<float4*>(&sB[brow][bcol]) = bv;
        __syncthreads();
#pragma unroll
        for (int k = 0; k < BK; k++) {
            float4 a4 = *reinterpret_cast<const float4*>(&sA[k][ty * 4]);
            float4 b4 = *reinterpret_cast<const float4*>(&sB[k][tx * 4]);
            float a[4] = {a4.x, a4.y, a4.z, a4.w};
            float b[4] = {b4.x, b4.y, b4.z, b4.w};
#pragma unroll
            for (int i = 0; i < 4; i++)
#pragma unroll
                for (int j = 0; j < 4; j++) acc[i][j] = fmaf(a[i], b[j], acc[i][j]);
        }
        __syncthreads();
    }
#pragma unroll
    for (int i = 0; i < 4; i++) {
        int r = bm + ty * 4 + i;
        if (r >= M) break;
#pragma unroll
        for (int j = 0; j < 4; j++) {
            int c = bn + tx * 4 + j;
            float v = acc[i][j];
            if (bias) v += bias[c];
            if (act) v = eluf(v);
            C[(size_t)r * Ncol + c] = v;
        }
    }
}

// ---------------- 96x128 SGEMM + attention epilogue (3 CTAs/SM, 3-stage cp.async) ----------------
#define TBM 96
#define TBN 128
#define TBK 16
#define TAPAD 100   // 400B row stride, 16B aligned

__global__ __launch_bounds__(256, 3) void gemm_att_kernel(
    const float* __restrict__ A, const float* __restrict__ B,
    float* __restrict__ C, const float* __restrict__ att_src,
    const float* __restrict__ att_dst, int M, int K) {
    __shared__ float sA[2][TBK][TAPAD];
    __shared__ float sB[3][TBK][TBN];
    __shared__ float s_as[TBN];
    __shared__ float s_ad[TBN];

    int tid = threadIdx.x;        // 256
    int bm = blockIdx.x * TBM;
    int bn = blockIdx.y * TBN;    // 0 or 128
    int w = tid >> 5;             // warp 0..7 -> rows 12w..12w+11
    int tx = tid & 31;            // cols bn + tx*4..+3

    if (tid < TBN) {
        s_as[tid] = att_src[bn + tid];
        s_ad[tid] = att_dst[bn + tid];
    }

    int arow = tid >> 1;          // 0..95 (valid when tid<192)
    int akc  = (tid & 1) * 8;     // 0 or 8
    bool aload = (tid < 192);
    int gr = bm + arow;
    bool avalid = aload && (gr < M);
    const float* Arow = A + (size_t)gr * K + akc;

    int lkb  = tid >> 4;          // 0..15
    int bcol = (tid & 15) * 8;    // 0..120
    const float* Bbase = B + (size_t)lkb * HCC + bn + bcol;

    ull acc[6][4];
#pragma unroll
    for (int p = 0; p < 6; p++)
#pragma unroll
        for (int j = 0; j < 4; j++) acc[p][j] = 0ull;

    const int T = K / TBK;

    float4 av0 = make_float4(0.f, 0.f, 0.f, 0.f);
    float4 av1 = make_float4(0.f, 0.f, 0.f, 0.f);
    if (avalid) {
        av0 = *reinterpret_cast<const float4*>(Arow);
        av1 = *reinterpret_cast<const float4*>(Arow + 4);
    }
    {
        unsigned d0 = smem_u32(&sB[0][lkb][bcol]);
        cpasync16(d0, Bbase);
        cpasync16(d0 + 16, Bbase + 4);
        asm volatile("cp.async.commit_group;");
        if (T > 1) {
            unsigned d1 = smem_u32(&sB[1][lkb][bcol]);
            const float* g1 = Bbase + (size_t)TBK * HCC;
            cpasync16(d1, g1);
            cpasync16(d1 + 16, g1 + 4);
            asm volatile("cp.async.commit_group;");
        }
    }

    int st = 0;
    int ab = 0;
    for (int t = 0; t < T; t++) {
        if (t + 1 < T) asm volatile("cp.async.wait_group 1;");
        else           asm volatile("cp.async.wait_group 0;");
        if (aload) {
            sA[ab][akc + 0][arow] = av0.x;
            sA[ab][akc + 1][arow] = av0.y;
            sA[ab][akc + 2][arow] = av0.z;
            sA[ab][akc + 3][arow] = av0.w;
            sA[ab][akc + 4][arow] = av1.x;
            sA[ab][akc + 5][arow] = av1.y;
            sA[ab][akc + 6][arow] = av1.z;
            sA[ab][akc + 7][arow] = av1.w;
        }
        __syncthreads();
        // issue B(t+2) EARLY: slot (st+2)%3 was last read during compute(t-1),
        // which every warp finished before the barrier above.
        if (t + 2 < T) {
            int ns = (st + 2 >= 3) ? st - 1 : st + 2;
            unsigned dn = smem_u32(&sB[ns][lkb][bcol]);
            const float* gn = Bbase + (size_t)(t + 2) * TBK * HCC;
            cpasync16(dn, gn);
            cpasync16(dn + 16, gn + 4);
        }
        asm volatile("cp.async.commit_group;");
        // prefetch A(t+1) into registers
        if (t + 1 < T && avalid) {
            av0 = *reinterpret_cast<const float4*>(Arow + (size_t)(t + 1) * TBK);
            av1 = *reinterpret_cast<const float4*>(Arow + (size_t)(t + 1) * TBK + 4);
        }
#pragma unroll
        for (int k = 0; k < TBK; k++) {
            longlong2 a01 = *reinterpret_cast<const longlong2*>(&sA[ab][k][w * 12]);
            longlong2 a23 = *reinterpret_cast<const longlong2*>(&sA[ab][k][w * 12 + 4]);
            longlong2 a45 = *reinterpret_cast<const longlong2*>(&sA[ab][k][w * 12 + 8]);
            float4 b4 = *reinterpret_cast<const float4*>(&sB[st][k][tx * 4]);
            ull ap[6] = {(ull)a01.x, (ull)a01.y, (ull)a23.x, (ull)a23.y, (ull)a45.x, (ull)a45.y};
            float b[4] = {b4.x, b4.y, b4.z, b4.w};
#pragma unroll
            for (int j = 0; j < 4; j++) {
                ull bd = dupf(b[j]);
#pragma unroll
                for (int p = 0; p < 6; p++) fma2(acc[p][j], ap[p], bd);
            }
        }
        st = (st + 1 == 3) ? 0 : st + 1;
        ab ^= 1;
    }

    int h = (bn >> 6) + (tx >> 4);
    float ws[4], wd[4];
#pragma unroll
    for (int q = 0; q < 4; q++) {
        ws[q] = s_as[tx * 4 + q];
        wd[q] = s_ad[tx * 4 + q];
    }

#pragma unroll
    for (int p = 0; p < 6; p++) {
#pragma unroll
        for (int half = 0; half < 2; half++) {
            int r = bm + w * 12 + 2 * p + half;
            float v[4];
            {
                float l0, h0, l1, h1, l2, h2, l3, h3;
                unpackf(acc[p][0], l0, h0);
                unpackf(acc[p][1], l1, h1);
                unpackf(acc[p][2], l2, h2);
                unpackf(acc[p][3], l3, h3);
                v[0] = half ? h0 : l0;
                v[1] = half ? h1 : l1;
                v[2] = half ? h2 : l2;
                v[3] = half ? h3 : l3;
            }
            float p1 = v[0] * ws[0] + v[1] * ws[1] + v[2] * ws[2] + v[3] * ws[3];
            float p2 = v[0] * wd[0] + v[1] * wd[1] + v[2] * wd[2] + v[3] * wd[3];
#pragma unroll
            for (int o = 8; o; o >>= 1) {
                p1 += __shfl_xor_sync(0xffffffffu, p1, o);
                p2 += __shfl_xor_sync(0xffffffffu, p2, o);
            }
            if (r < M) {
                if ((tx & 15) == 0) {
                    g_asrc[(size_t)r * HEADSC + h] = p1;
                    g_adst[(size_t)r * HEADSC + h] = p2;
                }
                *reinterpret_cast<float4*>(C + (size_t)r * HCC + bn + tx * 4) =
                    make_float4(v[0], v[1], v[2], v[3]);
            }
        }
    }
}

// ---------------- single-pass warp-per-dst GAT aggregation (measured optimum) ----------------
#define AGG_WARPS 8
__global__ __launch_bounds__(AGG_WARPS * 32) void gat_fused_kernel(
    const float* __restrict__ feat, const float* __restrict__ bias,
    float* __restrict__ out) {
    __shared__ float s_p[AGG_WARPS][32][HEADSC];
    __shared__ int s_src[AGG_WARPS][32];

    int wid = threadIdx.x >> 5;
    int lane = threadIdx.x & 31;
    int d = blockIdx.x * AGG_WARPS + wid;
    if (d >= NN) return;

    int base = g_off[d];
    int deg = g_off[d + 1] - base;
    int total = deg + 1;

    float4 ad4 = *reinterpret_cast<const float4*>(g_adst + (size_t)d * HEADSC);
    float adst[4] = {ad4.x, ad4.y, ad4.z, ad4.w};

    int myc = lane * 8;
    int myh = lane >> 3;
    float acc[8] = {0.f, 0.f, 0.f, 0.f, 0.f, 0.f, 0.f, 0.f};
    float denh[4] = {0.f, 0.f, 0.f, 0.f};

    for (int ch = 0; ch < total; ch += 32) {
        int j = ch + lane;
        if (j < total) {
            int s = (j < deg) ? g_srclist[base + j] : d;
            float4 as4 = *reinterpret_cast<const float4*>(g_asrc + (size_t)s * HEADSC);
            float p0 = __expf(lrelu(as4.x + adst[0]));
            float p1 = __expf(lrelu(as4.y + adst[1]));
            float p2 = __expf(lrelu(as4.z + adst[2]));
            float p3 = __expf(lrelu(as4.w + adst[3]));
            denh[0] += p0; denh[1] += p1; denh[2] += p2; denh[3] += p3;
            s_p[wid][lane][0] = p0;
            s_p[wid][lane][1] = p1;
            s_p[wid][lane][2] = p2;
            s_p[wid][lane][3] = p3;
            s_src[wid][lane] = s;
        }
        __syncwarp();
        int lim = min(32, total - ch);
        int jj = 0;
        for (; jj + 2 <= lim; jj += 2) {
            int s0 = s_src[wid][jj];
            int s1 = s_src[wid][jj + 1];
            float a0 = s_p[wid][jj][myh];
            float a1 = s_p[wid][jj + 1][myh];
            float4 f00 = *reinterpret_cast<const float4*>(feat + (size_t)s0 * HCC + myc);
            float4 f01 = *reinterpret_cast<const float4*>(feat + (size_t)s0 * HCC + myc + 4);
            float4 f10 = *reinterpret_cast<const float4*>(feat + (size_t)s1 * HCC + myc);
            float4 f11 = *reinterpret_cast<const float4*>(feat + (size_t)s1 * HCC + myc + 4);
            acc[0] = fmaf(a0, f00.x, acc[0]); acc[1] = fmaf(a0, f00.y, acc[1]);
            acc[2] = fmaf(a0, f00.z, acc[2]); acc[3] = fmaf(a0, f00.w, acc[3]);
            acc[4] = fmaf(a0, f01.x, acc[4]); acc[5] = fmaf(a0, f01.y, acc[5]);
            acc[6] = fmaf(a0, f01.z, acc[6]); acc[7] = fmaf(a0, f01.w, acc[7]);
            acc[0] = fmaf(a1, f10.x, acc[0]); acc[1] = fmaf(a1, f10.y, acc[1]);
            acc[2] = fmaf(a1, f10.z, acc[2]); acc[3] = fmaf(a1, f10.w, acc[3]);
            acc[4] = fmaf(a1, f11.x, acc[4]); acc[5] = fmaf(a1, f11.y, acc[5]);
            acc[6] = fmaf(a1, f11.z, acc[6]); acc[7] = fmaf(a1, f11.w, acc[7]);
        }
        for (; jj < lim; jj++) {
            int s0 = s_src[wid][jj];
            float a0 = s_p[wid][jj][myh];
            float4 f00 = *reinterpret_cast<const float4*>(feat + (size_t)s0 * HCC + myc);
            float4 f01 = *reinterpret_cast<const float4*>(feat + (size_t)s0 * HCC + myc + 4);
            acc[0] = fmaf(a0, f00.x, acc[0]); acc[1] = fmaf(a0, f00.y, acc[1]);
            acc[2] = fmaf(a0, f00.z, acc[2]); acc[3] = fmaf(a0, f00.w, acc[3]);
            acc[4] = fmaf(a0, f01.x, acc[4]); acc[5] = fmaf(a0, f01.y, acc[5]);
            acc[6] = fmaf(a0, f01.z, acc[6]); acc[7] = fmaf(a0, f01.w, acc[7]);
        }
        __syncwarp();
    }

#pragma unroll
    for (int o = 16; o; o >>= 1) {
#pragma unroll
        for (int h = 0; h < 4; h++) denh[h] += __shfl_xor_sync(0xffffffffu, denh[h], o);
    }
    float inv = 1.f / (denh[myh] + 1e-16f);

    float* orow = out + (size_t)d * HCC + myc;
    const float* brow = bias + myc;
    float4 b0 = *reinterpret_cast<const float4*>(brow);
    float4 b1 = *reinterpret_cast<const float4*>(brow + 4);
    float4 r0 = make_float4(eluf(acc[0] * inv + b0.x), eluf(acc[1] * inv + b0.y),
                            eluf(acc[2] * inv + b0.z), eluf(acc[3] * inv + b0.w));
    float4 r1 = make_float4(eluf(acc[4] * inv + b1.x), eluf(acc[5] * inv + b1.y),
                            eluf(acc[6] * inv + b1.z), eluf(acc[7] * inv + b1.w));
    *reinterpret_cast<float4*>(orow) = r0;
    *reinterpret_cast<float4*>(orow + 4) = r1;
}

// ---------------- fused out projection + layernorm, double-buffered ----------------
#define ONB 32
__global__ __launch_bounds__(256) void onl_kernel(
    const float* __restrict__ hin, const float* __restrict__ Wout,
    const float* __restrict__ bout, const float* __restrict__ gamma,
    const float* __restrict__ beta, float* __restrict__ out) {
    __shared__ float sA[2][32][ONB + 1];
    __shared__ float sB[2][32][OUT_DIMC];
    int tid = threadIdx.x;  // 256
    int bm = blockIdx.x * ONB;
    int ty = tid >> 5;
    int tx = tid & 31;

    int lrow = tid >> 3;
    int lkc  = (tid & 7) * 4;
    int lkb  = tid >> 3;
    int lc16 = (tid & 7) * 16;

    ull acc[4][2];
#pragma unroll
    for (int i = 0; i < 4; i++) { acc[i][0] = 0ull; acc[i][1] = 0ull; }

    const int T = HCC / 32;  // 8
    int gr = bm + lrow;
    float4 a_pre = (gr < NN) ? *reinterpret_cast<const float4*>(hin + (size_t)gr * HCC + lkc)
                             : make_float4(0.f, 0.f, 0.f, 0.f);
    float4 b_pre[4];
#pragma unroll
    for (int q = 0; q < 4; q++)
        b_pre[q] = *reinterpret_cast<const float4*>(Wout + (size_t)lkb * OUT_DIMC + lc16 + q * 4);

    sA[0][lkc + 0][lrow] = a_pre.x;
    sA[0][lkc + 1][lrow] = a_pre.y;
    sA[0][lkc + 2][lrow] = a_pre.z;
    sA[0][lkc + 3][lrow] = a_pre.w;
#pragma unroll
    for (int q = 0; q < 4; q++)
        *reinterpret_cast<float4*>(&sB[0][lkb][lc16 + q * 4]) = b_pre[q];
    __syncthreads();

    int buf = 0;
    for (int t = 0; t < T; t++) {
        if (t + 1 < T) {
            int k0 = (t + 1) * 32;
            a_pre = (gr < NN) ? *reinterpret_cast<const float4*>(hin + (size_t)gr * HCC + k0 + lkc)
                              : make_float4(0.f, 0.f, 0.f, 0.f);
#pragma unroll
            for (int q = 0; q < 4; q++)
                b_pre[q] = *reinterpret_cast<const float4*>(Wout + (size_t)(k0 + lkb) * OUT_DIMC + lc16 + q * 4);
        }
#pragma unroll 8
        for (int k = 0; k < 32; k++) {
            float4 b4 = *reinterpret_cast<const float4*>(&sB[buf][k][tx * 4]);
            ull bp0 = packf(b4.x, b4.y);
            ull bp1 = packf(b4.z, b4.w);
#pragma unroll
            for (int i = 0; i < 4; i++) {
                ull ad = dupf(sA[buf][k][ty * 4 + i]);
                fma2(acc[i][0], ad, bp0);
                fma2(acc[i][1], ad, bp1);
            }
        }
        if (t + 1 < T) {
            int nb = buf ^ 1;
            sA[nb][lkc + 0][lrow] = a_pre.x;
            sA[nb][lkc + 1][lrow] = a_pre.y;
            sA[nb][lkc + 2][lrow] = a_pre.z;
            sA[nb][lkc + 3][lrow] = a_pre.w;
#pragma unroll
            for (int q = 0; q < 4; q++)
                *reinterpret_cast<float4*>(&sB[nb][lkb][lc16 + q * 4]) = b_pre[q];
        }
        __syncthreads();
        buf ^= 1;
    }

    float b0 = bout[tx * 4 + 0], b1 = bout[tx * 4 + 1], b2 = bout[tx * 4 + 2], b3 = bout[tx * 4 + 3];
    float g0 = gamma[tx * 4 + 0], g1 = gamma[tx * 4 + 1], g2 = gamma[tx * 4 + 2], g3 = gamma[tx * 4 + 3];
    float be0 = beta[tx * 4 + 0], be1 = beta[tx * 4 + 1], be2 = beta[tx * 4 + 2], be3 = beta[tx * 4 + 3];
#pragma unroll
    for (int i = 0; i < 4; i++) {
        int r = bm + ty * 4 + i;
        float v[4];
        unpackf(acc[i][0], v[0], v[1]);
        unpackf(acc[i][1], v[2], v[3]);
        v[0] += b0; v[1] += b1; v[2] += b2; v[3] += b3;
        float psum = v[0] + v[1] + v[2] + v[3];
#pragma unroll
        for (int o = 16; o; o >>= 1) psum += __shfl_xor_sync(0xffffffffu, psum, o);
        float mu = psum * (1.f / OUT_DIMC);
        float d0 = v[0] - mu, d1 = v[1] - mu, d2 = v[2] - mu, d3 = v[3] - mu;
        float pss = d0 * d0 + d1 * d1 + d2 * d2 + d3 * d3;
#pragma unroll
        for (int o = 16; o; o >>= 1) pss += __shfl_xor_sync(0xffffffffu, pss, o);
        float inv = rsqrtf(pss * (1.f / OUT_DIMC) + LN_EPSF);
        if (r < NN) {
            float4 res = make_float4(d0 * inv * g0 + be0, d1 * inv * g1 + be1,
                                     d2 * inv * g2 + be2, d3 * inv * g3 + be3);
            *reinterpret_cast<float4*>(out + (size_t)r * OUT_DIMC + tx * 4) = res;
        }
    }
}

// ---------------- launch ----------------
extern "C" void kernel_launch(void* const* d_in, const int* in_sizes, int n_in,
                              void* d_out, int out_size) {
    const float* x     = (const float*)d_in[0];
    const int*   ei    = (const int*)d_in[1];
    const float* W_in  = (const float*)d_in[2];
    const float* b_in  = (const float*)d_in[3];
    const float* lin0  = (const float*)d_in[4];
    const float* att0s = (const float*)d_in[5];
    const float* att0d = (const float*)d_in[6];
    const float* bias0 = (const float*)d_in[7];
    const float* lin1  = (const float*)d_in[8];
    const float* att1s = (const float*)d_in[9];
    const float* att1d = (const float*)d_in[10];
    const float* bias1 = (const float*)d_in[11];
    const float* Wout  = (const float*)d_in[12];
    const float* bout  = (const float*)d_in[13];
    const float* gamma = (const float*)d_in[14];
    const float* beta  = (const float*)d_in[15];
    float* out = (float*)d_out;

    int E = in_sizes[1] / 2;
    if (E > EE) E = EE;
    const int* srcp = ei;
    const int* dstp = ei + E;

    float *h0p = nullptr, *featp = nullptr, *aggp = nullptr;
    cudaGetSymbolAddress((void**)&h0p, g_h0);
    cudaGetSymbolAddress((void**)&featp, g_feat);
    cudaGetSymbolAddress((void**)&aggp, g_agg);

    const int nsb = (NN + 255) / 256;
    const int gxa = (NN + TBM - 1) / TBM;
    const int gagg = (NN + AGG_WARPS - 1) / AGG_WARPS;

    // fork a side stream for the graph build so it overlaps the first GEMMs
    cudaStream_t s2;
    cudaStreamCreateWithFlags(&s2, cudaStreamNonBlocking);
    cudaEvent_t e0, e1;
    cudaEventCreateWithFlags(&e0, cudaEventDisableTiming);
    cudaEventCreateWithFlags(&e1, cudaEventDisableTiming);

    cudaEventRecord(e0, 0);
    cudaStreamWaitEvent(s2, e0, 0);

    zero_deg_kernel<<<nsb, 256, 0, s2>>>();
    count_deg_kernel<<<(E + 255) / 256, 256, 0, s2>>>(dstp, E);

    gemm_kernel<<<dim3((NN + BM - 1) / BM, HIDC / BN), 256>>>(
        x, W_in, b_in, h0p, NN, HIDC, IN_DIMC, 1);
    gemm_att_kernel<<<dim3(gxa, 2), 256>>>(h0p, lin0, featp, att0s, att0d, NN, HIDC);

    scan_p1_kernel<<<nsb, 256, 0, s2>>>();
    scan_p2_kernel<<<1, 256, 0, s2>>>(nsb);
    scan_p3_kernel<<<nsb, 256, 0, s2>>>();
    scatter_kernel<<<(E + 255) / 256, 256, 0, s2>>>(srcp, dstp, E);
    cudaEventRecord(e1, s2);
    cudaStreamWaitEvent(0, e1, 0);

    gat_fused_kernel<<<gagg, AGG_WARPS * 32>>>(featp, bias0, aggp);

    gemm_att_kernel<<<dim3(gxa, 2), 256>>>(aggp, lin1, featp, att1s, att1d, NN, HCC);
    gat_fused_kernel<<<gagg, AGG_WARPS * 32>>>(featp, bias1, aggp);

    onl_kernel<<<(NN + ONB - 1) / ONB, 256>>>(aggp, Wout, bout, gamma, beta, out);
}